// round 5
// baseline (speedup 1.0000x reference)
#include <cuda_runtime.h>
#include <cstddef>

// ---------------------------------------------------------------------------
// StackSAModuleMSG (PointNet++ SA module, multi-scale grouping), GB300 fp32.
//
// Fixed shapes: B=4, NB=8192 (xyz per batch), MB=2048 (queries per batch),
// M = B*MB = 8192 total queries, C_IN=64, CIN=67 (=3+64).
// Scale 0: radius 0.2, nsample 16.  Scale 1: radius 0.4, nsample 32.
//
// Pipeline per scale:
//   ballquery  -> g_idx (M*NS), -1 sentinel for empty groups
//   gemm1      -> X0 = gather(G) @ W0^T   (gather fused into A-tile build)
//   zero+stats -> per-channel sum / sumsq of X0
//   finalize   -> scale/shift for BN (train-mode: mean/var over all rows)
//   gemm2      -> X1 = relu(bn(X0)) @ W1^T  (BN+ReLU fused into A-load)
//   zero+stats+finalize on X1
//   maxpool    -> out[:, s*128:(s+1)*128] = max_j relu(bn(X1))
// ---------------------------------------------------------------------------

#define MTOT 8192          // total query points
#define NPB  8192          // xyz points per batch
#define NOUT 128           // channels per layer

// scratch (device globals: allocation-free contract)
__device__ float g_X0[262144 * 128];
__device__ float g_X1[262144 * 128];
__device__ int   g_idx[8192 * 32];
__device__ float g_sum[128];
__device__ float g_sq[128];
__device__ float g_scale[128];
__device__ float g_shift[128];

// ---------------------------------------------------------------------------
// Ball query: one warp per query point. Scan xyz in index order, collect the
// first NS in-ball indices (matches jnp.sort-of-order-key semantics), early
// exit. Pad with first hit; all -1 if empty.
// ---------------------------------------------------------------------------
template <int NS>
__global__ void ballquery_kernel(const float* __restrict__ xyz,
                                 const float* __restrict__ newxyz,
                                 float r2, int* __restrict__ idx_out) {
    int gw   = (blockIdx.x * blockDim.x + threadIdx.x) >> 5;
    int lane = threadIdx.x & 31;
    if (gw >= MTOT) return;
    int b = gw >> 11;  // / 2048
    float qx = newxyz[gw * 3 + 0];
    float qy = newxyz[gw * 3 + 1];
    float qz = newxyz[gw * 3 + 2];
    float qq = __fadd_rn(__fadd_rn(__fmul_rn(qx, qx), __fmul_rn(qy, qy)),
                         __fmul_rn(qz, qz));
    const float* P = xyz + (size_t)b * NPB * 3;
    int cnt = 0;
    int first = -1;
    for (int start = 0; start < NPB; start += 32) {
        int i = start + lane;
        float px = P[i * 3 + 0];
        float py = P[i * 3 + 1];
        float pz = P[i * 3 + 2];
        float pp = __fadd_rn(__fadd_rn(__fmul_rn(px, px), __fmul_rn(py, py)),
                             __fmul_rn(pz, pz));
        float dt = __fadd_rn(__fadd_rn(__fmul_rn(qx, px), __fmul_rn(qy, py)),
                             __fmul_rn(qz, pz));
        float d2 = __fsub_rn(__fadd_rn(qq, pp), __fmul_rn(2.0f, dt));
        bool in = d2 < r2;
        unsigned mask = __ballot_sync(0xFFFFFFFFu, in);
        if (mask) {
            if (first < 0) first = start + (__ffs(mask) - 1);
            int pos = cnt + __popc(mask & ((1u << lane) - 1u));
            if (in && pos < NS) idx_out[gw * NS + pos] = i;
            cnt += __popc(mask);
            if (cnt >= NS) break;
        }
    }
    if (cnt == 0) {
        for (int j = lane; j < NS; j += 32) idx_out[gw * NS + j] = -1;
    } else if (cnt < NS) {
        for (int j = cnt + lane; j < NS; j += 32) idx_out[gw * NS + j] = first;
    }
}

// ---------------------------------------------------------------------------
// GEMM1: X0[R,128] = G[R,67] @ W0^T, G gathered on the fly.
// Block: 64 rows x 128 cols, 256 threads, thread = 8 rows x 4 (lane-strided)
// cols. W in smem transposed [c][o] with pitch 129 (conflict-free).
// ---------------------------------------------------------------------------
#define SMEM1 ((67 * 129 + 64 * 68) * 4)

template <int NS>
__global__ __launch_bounds__(256) void gemm1_kernel(
    const float* __restrict__ xyz, const float* __restrict__ feat,
    const float* __restrict__ newxyz, const int* __restrict__ idx,
    const float* __restrict__ w0, float* __restrict__ X0) {
    extern __shared__ float sh[];
    float* Ws = sh;              // [67][129]
    float* Gs = sh + 67 * 129;   // [64][68]
    int tid = threadIdx.x;

    for (int i = tid; i < 128 * 67; i += 256) {
        int o = i / 67;
        int c = i - o * 67;
        Ws[c * 129 + o] = w0[i];
    }

    int row0 = blockIdx.x * 64;
    {
        int r  = tid >> 2;
        int lw = tid & 3;
        int rg = row0 + r;
        int m  = rg / NS;
        int p  = idx[rg];
        float* grow = Gs + r * 68;
        if (p < 0) {
            for (int c = lw; c < 67; c += 4) grow[c] = 0.0f;
        } else {
            int gp = ((m >> 11) << 13) + p;  // batch*8192 + local idx
            if (lw == 0) {
                grow[0] = xyz[gp * 3 + 0] - newxyz[m * 3 + 0];
                grow[1] = xyz[gp * 3 + 1] - newxyz[m * 3 + 1];
                grow[2] = xyz[gp * 3 + 2] - newxyz[m * 3 + 2];
            }
            const float4* frow = (const float4*)(feat + (size_t)gp * 64);
            for (int f = lw; f < 16; f += 4) {
                float4 v = frow[f];
                grow[3 + 4 * f + 0] = v.x;
                grow[3 + 4 * f + 1] = v.y;
                grow[3 + 4 * f + 2] = v.z;
                grow[3 + 4 * f + 3] = v.w;
            }
        }
    }
    __syncthreads();

    int lane = tid & 31;
    int r0   = (tid >> 5) * 8;
    float acc[8][4];
#pragma unroll
    for (int a = 0; a < 8; a++)
#pragma unroll
        for (int bb = 0; bb < 4; bb++) acc[a][bb] = 0.0f;

#pragma unroll 4
    for (int c = 0; c < 67; ++c) {
        float bv0 = Ws[c * 129 + lane];
        float bv1 = Ws[c * 129 + lane + 32];
        float bv2 = Ws[c * 129 + lane + 64];
        float bv3 = Ws[c * 129 + lane + 96];
#pragma unroll
        for (int rr = 0; rr < 8; ++rr) {
            float a = Gs[(r0 + rr) * 68 + c];
            acc[rr][0] = fmaf(a, bv0, acc[rr][0]);
            acc[rr][1] = fmaf(a, bv1, acc[rr][1]);
            acc[rr][2] = fmaf(a, bv2, acc[rr][2]);
            acc[rr][3] = fmaf(a, bv3, acc[rr][3]);
        }
    }
#pragma unroll
    for (int rr = 0; rr < 8; ++rr) {
        float* orow = X0 + (size_t)(row0 + r0 + rr) * 128;
        orow[lane]      = acc[rr][0];
        orow[lane + 32] = acc[rr][1];
        orow[lane + 64] = acc[rr][2];
        orow[lane + 96] = acc[rr][3];
    }
}

// ---------------------------------------------------------------------------
// GEMM2: X1[R,128] = relu(bn(X0)) @ W1^T. BN+ReLU fused into A-tile load.
// ---------------------------------------------------------------------------
#define SMEM2 ((128 * 129 + 64 * 128 + 256) * 4)

__global__ __launch_bounds__(256) void gemm2_kernel(
    const float* __restrict__ Xin, const float* __restrict__ w1,
    float* __restrict__ Xout) {
    extern __shared__ float sh[];
    float* Ws = sh;                    // [128][129]
    float* As = sh + 128 * 129;        // [64][128]
    float* sc = As + 64 * 128;         // [128]
    float* sf = sc + 128;              // [128]
    int tid = threadIdx.x;

    if (tid < 128) {
        sc[tid] = g_scale[tid];
        sf[tid] = g_shift[tid];
    }
    for (int i = tid; i < 128 * 128; i += 256) {
        int o = i >> 7;
        int k = i & 127;
        Ws[k * 129 + o] = w1[i];
    }
    __syncthreads();

    int row0 = blockIdx.x * 64;
    for (int i = tid; i < 64 * 128; i += 256) {
        int r = i >> 7;
        int k = i & 127;
        float v = Xin[(size_t)(row0 + r) * 128 + k];
        As[i] = fmaxf(fmaf(sc[k], v, sf[k]), 0.0f);
    }
    __syncthreads();

    int lane = tid & 31;
    int r0   = (tid >> 5) * 8;
    float acc[8][4];
#pragma unroll
    for (int a = 0; a < 8; a++)
#pragma unroll
        for (int bb = 0; bb < 4; bb++) acc[a][bb] = 0.0f;

#pragma unroll 4
    for (int k = 0; k < 128; ++k) {
        float bv0 = Ws[k * 129 + lane];
        float bv1 = Ws[k * 129 + lane + 32];
        float bv2 = Ws[k * 129 + lane + 64];
        float bv3 = Ws[k * 129 + lane + 96];
#pragma unroll
        for (int rr = 0; rr < 8; ++rr) {
            float a = As[(r0 + rr) * 128 + k];
            acc[rr][0] = fmaf(a, bv0, acc[rr][0]);
            acc[rr][1] = fmaf(a, bv1, acc[rr][1]);
            acc[rr][2] = fmaf(a, bv2, acc[rr][2]);
            acc[rr][3] = fmaf(a, bv3, acc[rr][3]);
        }
    }
#pragma unroll
    for (int rr = 0; rr < 8; ++rr) {
        float* orow = Xout + (size_t)(row0 + r0 + rr) * 128;
        orow[lane]      = acc[rr][0];
        orow[lane + 32] = acc[rr][1];
        orow[lane + 64] = acc[rr][2];
        orow[lane + 96] = acc[rr][3];
    }
}

// ---------------------------------------------------------------------------
// Per-channel sum / sumsq over R rows x 128 channels (block partials +
// shared atomics + global atomics).
// ---------------------------------------------------------------------------
__global__ void zero_stats_kernel() {
    int t = threadIdx.x;
    g_sum[t] = 0.0f;
    g_sq[t]  = 0.0f;
}

__global__ void stats_kernel(const float* __restrict__ X, int R) {
    __shared__ float s_sum[128];
    __shared__ float s_sq[128];
    int tid = threadIdx.x;  // 256
    if (tid < 128) {
        s_sum[tid] = 0.0f;
        s_sq[tid]  = 0.0f;
    }
    __syncthreads();
    int c    = tid & 127;
    int half = tid >> 7;
    float lsum = 0.0f, lsq = 0.0f;
    for (int r = blockIdx.x * 2 + half; r < R; r += gridDim.x * 2) {
        float v = X[(size_t)r * 128 + c];
        lsum += v;
        lsq  = fmaf(v, v, lsq);
    }
    atomicAdd(&s_sum[c], lsum);
    atomicAdd(&s_sq[c], lsq);
    __syncthreads();
    if (tid < 128) {
        atomicAdd(&g_sum[tid], s_sum[tid]);
        atomicAdd(&g_sq[tid], s_sq[tid]);
    }
}

__global__ void finalize_kernel(const float* __restrict__ gamma,
                                const float* __restrict__ beta, float invR) {
    int c = threadIdx.x;
    float mean = g_sum[c] * invR;
    float var  = g_sq[c] * invR - mean * mean;
    float s    = gamma[c] * rsqrtf(var + 1e-5f);
    g_scale[c] = s;
    g_shift[c] = fmaf(-mean, s, beta[c]);
}

// ---------------------------------------------------------------------------
// BN + ReLU + max over NS samples -> out columns [colBase, colBase+128)
// out row pitch = 256 (f0 | f1 concat).
// ---------------------------------------------------------------------------
template <int NS>
__global__ void maxpool_kernel(const float* __restrict__ X,
                               float* __restrict__ out, int colBase) {
    int t = blockIdx.x * blockDim.x + threadIdx.x;
    if (t >= MTOT * 128) return;
    int m = t >> 7;
    int c = t & 127;
    float s = g_scale[c];
    float b = g_shift[c];
    float mx = -3.0e38f;
    const float* px = X + (size_t)m * NS * 128 + c;
#pragma unroll
    for (int j = 0; j < NS; ++j) {
        mx = fmaxf(mx, fmaf(s, px[j * 128], b));
    }
    out[(size_t)m * 256 + colBase + c] = fmaxf(mx, 0.0f);
}

__global__ void copy_kernel(const float* __restrict__ src,
                            float* __restrict__ dst, int n) {
    int t = blockIdx.x * blockDim.x + threadIdx.x;
    if (t < n) dst[t] = src[t];
}

// ---------------------------------------------------------------------------
extern "C" void kernel_launch(void* const* d_in, const int* in_sizes, int n_in,
                              void* d_out, int out_size) {
    const float* xyz  = (const float*)d_in[0];
    const float* feat = (const float*)d_in[1];
    const float* nxyz = (const float*)d_in[2];
    // scale 0 params
    const float* w00 = (const float*)d_in[5];
    const float* g00 = (const float*)d_in[6];
    const float* b00 = (const float*)d_in[7];
    const float* w01 = (const float*)d_in[8];
    const float* g01 = (const float*)d_in[9];
    const float* b01 = (const float*)d_in[10];
    // scale 1 params
    const float* w10 = (const float*)d_in[11];
    const float* g10 = (const float*)d_in[12];
    const float* b10 = (const float*)d_in[13];
    const float* w11 = (const float*)d_in[14];
    const float* g11 = (const float*)d_in[15];
    const float* b11 = (const float*)d_in[16];

    float* outBase = (float*)d_out;
    int featOff = out_size - MTOT * 256;  // tuple output: new_xyz then features
    if (featOff > 0) {
        copy_kernel<<<(featOff + 255) / 256, 256>>>(nxyz, outBase, featOff);
    }
    float* outF = outBase + (featOff > 0 ? featOff : 0);

    cudaFuncSetAttribute(gemm1_kernel<16>,
                         cudaFuncAttributeMaxDynamicSharedMemorySize, SMEM1);
    cudaFuncSetAttribute(gemm1_kernel<32>,
                         cudaFuncAttributeMaxDynamicSharedMemorySize, SMEM1);
    cudaFuncSetAttribute(gemm2_kernel,
                         cudaFuncAttributeMaxDynamicSharedMemorySize, SMEM2);

    float* X0p;
    float* X1p;
    int* idxp;
    cudaGetSymbolAddress((void**)&X0p, g_X0);
    cudaGetSymbolAddress((void**)&X1p, g_X1);
    cudaGetSymbolAddress((void**)&idxp, g_idx);

    const float r2_0 = (float)(0.2 * 0.2);
    const float r2_1 = (float)(0.4 * 0.4);

    // ---------------- scale 0 (NS=16) ----------------
    {
        const int NS = 16;
        const int R  = MTOT * NS;  // 131072
        ballquery_kernel<16><<<MTOT * 32 / 256, 256>>>(xyz, nxyz, r2_0, idxp);
        gemm1_kernel<16><<<R / 64, 256, SMEM1>>>(xyz, feat, nxyz, idxp, w00, X0p);
        zero_stats_kernel<<<1, 128>>>();
        stats_kernel<<<512, 256>>>(X0p, R);
        finalize_kernel<<<1, 128>>>(g00, b00, 1.0f / (float)R);
        gemm2_kernel<<<R / 64, 256, SMEM2>>>(X0p, w01, X1p);
        zero_stats_kernel<<<1, 128>>>();
        stats_kernel<<<512, 256>>>(X1p, R);
        finalize_kernel<<<1, 128>>>(g01, b01, 1.0f / (float)R);
        maxpool_kernel<16><<<MTOT * 128 / 256, 256>>>(X1p, outF, 0);
    }

    // ---------------- scale 1 (NS=32) ----------------
    {
        const int NS = 32;
        const int R  = MTOT * NS;  // 262144
        ballquery_kernel<32><<<MTOT * 32 / 256, 256>>>(xyz, nxyz, r2_1, idxp);
        gemm1_kernel<32><<<R / 64, 256, SMEM1>>>(xyz, feat, nxyz, idxp, w10, X0p);
        zero_stats_kernel<<<1, 128>>>();
        stats_kernel<<<512, 256>>>(X0p, R);
        finalize_kernel<<<1, 128>>>(g10, b10, 1.0f / (float)R);
        gemm2_kernel<<<R / 64, 256, SMEM2>>>(X0p, w11, X1p);
        zero_stats_kernel<<<1, 128>>>();
        stats_kernel<<<512, 256>>>(X1p, R);
        finalize_kernel<<<1, 128>>>(g11, b11, 1.0f / (float)R);
        maxpool_kernel<32><<<MTOT * 128 / 256, 256>>>(X1p, outF, 128);
    }
}

// round 6
// speedup vs baseline: 2.2885x; 2.2885x over previous
#include <cuda_runtime.h>
#include <cstddef>

// ---------------------------------------------------------------------------
// StackSAModuleMSG — tf32 tensor-core version.
// B=4, NB=8192, MB=2048, M=8192, C_IN=64, CIN=67.
// Scale 0: r=0.2, NS=16.  Scale 1: r=0.4, NS=32.
//
// Per scale:
//   ballquery -> idx
//   zero_stats
//   gemm1_tc  : X0 = gather(G) @ W0^T  (HMMA tf32; stats fused in epilogue)
//   finalize  : BN scale/shift (layer0)
//   zero_stats
//   gemm2_tc  : X1 = relu(bn(X0)) @ W1^T (BN fused into A-load; stats fused)
//   finalize  : BN scale/shift (layer1)
//   maxpool   : out = max_j relu(bn(X1))
// ---------------------------------------------------------------------------

#define MTOT 8192
#define NPB  8192

__device__ float g_X0[262144 * 128];
__device__ float g_X1[262144 * 128];
__device__ int   g_idx[8192 * 32];
__device__ float g_sum[128];
__device__ float g_sq[128];
__device__ float g_scale[128];
__device__ float g_shift[128];

__device__ __forceinline__ unsigned f2tf(float f) {
    unsigned r;
    asm("cvt.rna.tf32.f32 %0, %1;" : "=r"(r) : "f"(f));
    return r;
}

__device__ __forceinline__ void mma_tf32(float c[4], const unsigned a[4],
                                         unsigned b0, unsigned b1) {
    asm volatile(
        "mma.sync.aligned.m16n8k8.row.col.f32.tf32.tf32.f32 "
        "{%0,%1,%2,%3}, {%4,%5,%6,%7}, {%8,%9}, {%0,%1,%2,%3};"
        : "+f"(c[0]), "+f"(c[1]), "+f"(c[2]), "+f"(c[3])
        : "r"(a[0]), "r"(a[1]), "r"(a[2]), "r"(a[3]), "r"(b0), "r"(b1));
}

// ---------------------------------------------------------------------------
// Ball query: one warp per query; exact fp32 arithmetic (must match reference
// membership bit-for-bit). Collect first NS in-index-order hits, early exit.
// ---------------------------------------------------------------------------
template <int NS>
__global__ void ballquery_kernel(const float* __restrict__ xyz,
                                 const float* __restrict__ newxyz,
                                 float r2, int* __restrict__ idx_out) {
    int gw   = (blockIdx.x * blockDim.x + threadIdx.x) >> 5;
    int lane = threadIdx.x & 31;
    if (gw >= MTOT) return;
    int b = gw >> 11;
    float qx = newxyz[gw * 3 + 0];
    float qy = newxyz[gw * 3 + 1];
    float qz = newxyz[gw * 3 + 2];
    float qq = __fadd_rn(__fadd_rn(__fmul_rn(qx, qx), __fmul_rn(qy, qy)),
                         __fmul_rn(qz, qz));
    const float* P = xyz + (size_t)b * NPB * 3;
    int cnt = 0;
    int first = -1;
    for (int start = 0; start < NPB; start += 32) {
        int i = start + lane;
        float px = P[i * 3 + 0];
        float py = P[i * 3 + 1];
        float pz = P[i * 3 + 2];
        float pp = __fadd_rn(__fadd_rn(__fmul_rn(px, px), __fmul_rn(py, py)),
                             __fmul_rn(pz, pz));
        float dt = __fadd_rn(__fadd_rn(__fmul_rn(qx, px), __fmul_rn(qy, py)),
                             __fmul_rn(qz, pz));
        float d2 = __fsub_rn(__fadd_rn(qq, pp), __fmul_rn(2.0f, dt));
        bool in = d2 < r2;
        unsigned mask = __ballot_sync(0xFFFFFFFFu, in);
        if (mask) {
            if (first < 0) first = start + (__ffs(mask) - 1);
            int pos = cnt + __popc(mask & ((1u << lane) - 1u));
            if (in && pos < NS) idx_out[gw * NS + pos] = i;
            cnt += __popc(mask);
            if (cnt >= NS) break;
        }
    }
    if (cnt == 0) {
        for (int j = lane; j < NS; j += 32) idx_out[gw * NS + j] = -1;
    } else if (cnt < NS) {
        for (int j = cnt + lane; j < NS; j += 32) idx_out[gw * NS + j] = first;
    }
}

// ---------------------------------------------------------------------------
// GEMM1 (tensor): X0[R,128] = G[R,67] @ W0^T, gather fused, K padded to 72.
// Block 128 rows x 128 cols, 8 warps (4x2), warp tile 32x64 (2x8 mma tiles).
// Pitch 76 (76%32==4 -> conflict-free frag loads). Stats fused.
// ---------------------------------------------------------------------------
#define PA1 76
#define KP1 72
#define SMEM1B ((128 * PA1 * 2 + 256) * 4)

template <int NS>
__global__ __launch_bounds__(256) void gemm1_tc(
    const float* __restrict__ xyz, const float* __restrict__ feat,
    const float* __restrict__ newxyz, const int* __restrict__ idx,
    const float* __restrict__ w0, float* __restrict__ X0) {
    extern __shared__ unsigned sh[];
    unsigned* As = sh;                       // [128][76]
    unsigned* Ws = sh + 128 * PA1;           // [128][76]  (W[o][c])
    float* s_sum = (float*)(Ws + 128 * PA1); // [128]
    float* s_sq  = s_sum + 128;              // [128]
    int tid = threadIdx.x;

    if (tid < 128) { s_sum[tid] = 0.0f; s_sq[tid] = 0.0f; }
    for (int i = tid; i < 128 * KP1; i += 256) {
        int o = i / KP1;
        int c = i - o * KP1;
        Ws[o * PA1 + c] = (c < 67) ? f2tf(w0[o * 67 + c]) : 0u;
    }

    int row0 = blockIdx.x * 128;
    {
        int r = tid >> 1, lw = tid & 1;
        int rg = row0 + r;
        int m = rg / NS;
        int p = idx[rg];
        unsigned* grow = As + r * PA1;
        if (p < 0) {
#pragma unroll
            for (int c = 0; c < 36; ++c) grow[lw * 36 + c] = 0u;
        } else {
            int gp = ((m >> 11) << 13) + p;
            if (lw == 0) {
                grow[0] = f2tf(xyz[gp * 3 + 0] - newxyz[m * 3 + 0]);
                grow[1] = f2tf(xyz[gp * 3 + 1] - newxyz[m * 3 + 1]);
                grow[2] = f2tf(xyz[gp * 3 + 2] - newxyz[m * 3 + 2]);
            } else {
                grow[67] = 0u; grow[68] = 0u; grow[69] = 0u;
                grow[70] = 0u; grow[71] = 0u;
            }
            const float4* frow = (const float4*)(feat + (size_t)gp * 64);
            for (int f = lw; f < 16; f += 2) {
                float4 v = frow[f];
                grow[3 + 4 * f + 0] = f2tf(v.x);
                grow[3 + 4 * f + 1] = f2tf(v.y);
                grow[3 + 4 * f + 2] = f2tf(v.z);
                grow[3 + 4 * f + 3] = f2tf(v.w);
            }
        }
    }
    __syncthreads();

    int lane = tid & 31;
    int wid  = tid >> 5;
    int wm = wid & 3, wn = wid >> 2;
    int gid = lane >> 2, t4 = lane & 3;

    float acc[2][8][4];
#pragma unroll
    for (int mt = 0; mt < 2; ++mt)
#pragma unroll
        for (int nt = 0; nt < 8; ++nt)
#pragma unroll
            for (int j = 0; j < 4; ++j) acc[mt][nt][j] = 0.0f;

#pragma unroll
    for (int ks = 0; ks < 9; ++ks) {
        int k0 = ks * 8;
        unsigned a[2][4];
#pragma unroll
        for (int mt = 0; mt < 2; ++mt) {
            const unsigned* ap = As + (wm * 32 + mt * 16 + gid) * PA1 + k0 + t4;
            a[mt][0] = ap[0];
            a[mt][1] = ap[8 * PA1];
            a[mt][2] = ap[4];
            a[mt][3] = ap[8 * PA1 + 4];
        }
#pragma unroll
        for (int nt = 0; nt < 8; ++nt) {
            const unsigned* bp = Ws + (wn * 64 + nt * 8 + gid) * PA1 + k0 + t4;
            unsigned b0 = bp[0], b1 = bp[4];
            mma_tf32(acc[0][nt], a[0], b0, b1);
            mma_tf32(acc[1][nt], a[1], b0, b1);
        }
    }

    // store
#pragma unroll
    for (int mt = 0; mt < 2; ++mt) {
        int rbase = row0 + wm * 32 + mt * 16 + gid;
#pragma unroll
        for (int nt = 0; nt < 8; ++nt) {
            int cc = wn * 64 + nt * 8 + t4 * 2;
            *(float2*)(X0 + (size_t)rbase * 128 + cc) =
                make_float2(acc[mt][nt][0], acc[mt][nt][1]);
            *(float2*)(X0 + (size_t)(rbase + 8) * 128 + cc) =
                make_float2(acc[mt][nt][2], acc[mt][nt][3]);
        }
    }
    // fused BN stats: reduce over rows (2 mt x 2 halves x 8 lane-groups)
#pragma unroll
    for (int nt = 0; nt < 8; ++nt) {
#pragma unroll
        for (int j = 0; j < 2; ++j) {
            float v0 = acc[0][nt][j], v1 = acc[0][nt][j + 2];
            float v2 = acc[1][nt][j], v3 = acc[1][nt][j + 2];
            float s = v0 + v1 + v2 + v3;
            float q = v0 * v0 + v1 * v1 + v2 * v2 + v3 * v3;
#pragma unroll
            for (int o = 4; o <= 16; o <<= 1) {
                s += __shfl_xor_sync(0xFFFFFFFFu, s, o);
                q += __shfl_xor_sync(0xFFFFFFFFu, q, o);
            }
            if (gid == 0) {
                int c = wn * 64 + nt * 8 + t4 * 2 + j;
                atomicAdd(&s_sum[c], s);
                atomicAdd(&s_sq[c], q);
            }
        }
    }
    __syncthreads();
    if (tid < 128) {
        atomicAdd(&g_sum[tid], s_sum[tid]);
        atomicAdd(&g_sq[tid], s_sq[tid]);
    }
}

// ---------------------------------------------------------------------------
// GEMM2 (tensor): X1[R,128] = relu(bn(X0)) @ W1^T, K=128. Pitch 132.
// BN+ReLU fused into A-fill; stats fused in epilogue.
// ---------------------------------------------------------------------------
#define PA2 132
#define SMEM2B ((128 * PA2 * 2 + 512) * 4)

__global__ __launch_bounds__(256) void gemm2_tc(
    const float* __restrict__ Xin, const float* __restrict__ w1,
    float* __restrict__ Xout) {
    extern __shared__ unsigned sh[];
    unsigned* As = sh;                        // [128][132]
    unsigned* Ws = sh + 128 * PA2;            // [128][132]
    float* s_sum = (float*)(Ws + 128 * PA2);  // [128]
    float* s_sq  = s_sum + 128;
    float* sc    = s_sq + 128;
    float* sf    = sc + 128;
    int tid = threadIdx.x;

    if (tid < 128) {
        s_sum[tid] = 0.0f; s_sq[tid] = 0.0f;
        sc[tid] = g_scale[tid]; sf[tid] = g_shift[tid];
    }
    for (int i = tid; i < 128 * 128; i += 256) {
        int o = i >> 7, k = i & 127;
        Ws[o * PA2 + k] = f2tf(w1[i]);
    }
    __syncthreads();

    int row0 = blockIdx.x * 128;
    for (int i = tid; i < 128 * 32; i += 256) {
        int r = i >> 5, kq = (i & 31) << 2;
        float4 v = *(const float4*)(Xin + (size_t)(row0 + r) * 128 + kq);
        uint4 u;
        u.x = f2tf(fmaxf(fmaf(sc[kq + 0], v.x, sf[kq + 0]), 0.0f));
        u.y = f2tf(fmaxf(fmaf(sc[kq + 1], v.y, sf[kq + 1]), 0.0f));
        u.z = f2tf(fmaxf(fmaf(sc[kq + 2], v.z, sf[kq + 2]), 0.0f));
        u.w = f2tf(fmaxf(fmaf(sc[kq + 3], v.w, sf[kq + 3]), 0.0f));
        *(uint4*)(As + r * PA2 + kq) = u;
    }
    __syncthreads();

    int lane = tid & 31;
    int wid  = tid >> 5;
    int wm = wid & 3, wn = wid >> 2;
    int gid = lane >> 2, t4 = lane & 3;

    float acc[2][8][4];
#pragma unroll
    for (int mt = 0; mt < 2; ++mt)
#pragma unroll
        for (int nt = 0; nt < 8; ++nt)
#pragma unroll
            for (int j = 0; j < 4; ++j) acc[mt][nt][j] = 0.0f;

#pragma unroll
    for (int ks = 0; ks < 16; ++ks) {
        int k0 = ks * 8;
        unsigned a[2][4];
#pragma unroll
        for (int mt = 0; mt < 2; ++mt) {
            const unsigned* ap = As + (wm * 32 + mt * 16 + gid) * PA2 + k0 + t4;
            a[mt][0] = ap[0];
            a[mt][1] = ap[8 * PA2];
            a[mt][2] = ap[4];
            a[mt][3] = ap[8 * PA2 + 4];
        }
#pragma unroll
        for (int nt = 0; nt < 8; ++nt) {
            const unsigned* bp = Ws + (wn * 64 + nt * 8 + gid) * PA2 + k0 + t4;
            unsigned b0 = bp[0], b1 = bp[4];
            mma_tf32(acc[0][nt], a[0], b0, b1);
            mma_tf32(acc[1][nt], a[1], b0, b1);
        }
    }

#pragma unroll
    for (int mt = 0; mt < 2; ++mt) {
        int rbase = row0 + wm * 32 + mt * 16 + gid;
#pragma unroll
        for (int nt = 0; nt < 8; ++nt) {
            int cc = wn * 64 + nt * 8 + t4 * 2;
            *(float2*)(Xout + (size_t)rbase * 128 + cc) =
                make_float2(acc[mt][nt][0], acc[mt][nt][1]);
            *(float2*)(Xout + (size_t)(rbase + 8) * 128 + cc) =
                make_float2(acc[mt][nt][2], acc[mt][nt][3]);
        }
    }
#pragma unroll
    for (int nt = 0; nt < 8; ++nt) {
#pragma unroll
        for (int j = 0; j < 2; ++j) {
            float v0 = acc[0][nt][j], v1 = acc[0][nt][j + 2];
            float v2 = acc[1][nt][j], v3 = acc[1][nt][j + 2];
            float s = v0 + v1 + v2 + v3;
            float q = v0 * v0 + v1 * v1 + v2 * v2 + v3 * v3;
#pragma unroll
            for (int o = 4; o <= 16; o <<= 1) {
                s += __shfl_xor_sync(0xFFFFFFFFu, s, o);
                q += __shfl_xor_sync(0xFFFFFFFFu, q, o);
            }
            if (gid == 0) {
                int c = wn * 64 + nt * 8 + t4 * 2 + j;
                atomicAdd(&s_sum[c], s);
                atomicAdd(&s_sq[c], q);
            }
        }
    }
    __syncthreads();
    if (tid < 128) {
        atomicAdd(&g_sum[tid], s_sum[tid]);
        atomicAdd(&g_sq[tid], s_sq[tid]);
    }
}

// ---------------------------------------------------------------------------
__global__ void zero_stats_kernel() {
    int t = threadIdx.x;
    g_sum[t] = 0.0f;
    g_sq[t]  = 0.0f;
}

__global__ void finalize_kernel(const float* __restrict__ gamma,
                                const float* __restrict__ beta, float invR) {
    int c = threadIdx.x;
    float mean = g_sum[c] * invR;
    float var  = g_sq[c] * invR - mean * mean;
    float s    = gamma[c] * rsqrtf(var + 1e-5f);
    g_scale[c] = s;
    g_shift[c] = fmaf(-mean, s, beta[c]);
}

template <int NS>
__global__ void maxpool_kernel(const float* __restrict__ X,
                               float* __restrict__ out, int colBase) {
    int t = blockIdx.x * blockDim.x + threadIdx.x;
    if (t >= MTOT * 128) return;
    int m = t >> 7;
    int c = t & 127;
    float s = g_scale[c];
    float b = g_shift[c];
    float mx = -3.0e38f;
    const float* px = X + (size_t)m * NS * 128 + c;
#pragma unroll
    for (int j = 0; j < NS; ++j) mx = fmaxf(mx, fmaf(s, px[j * 128], b));
    out[(size_t)m * 256 + colBase + c] = fmaxf(mx, 0.0f);
}

__global__ void copy_kernel(const float* __restrict__ src,
                            float* __restrict__ dst, int n) {
    int t = blockIdx.x * blockDim.x + threadIdx.x;
    if (t < n) dst[t] = src[t];
}

// ---------------------------------------------------------------------------
extern "C" void kernel_launch(void* const* d_in, const int* in_sizes, int n_in,
                              void* d_out, int out_size) {
    const float* xyz  = (const float*)d_in[0];
    const float* feat = (const float*)d_in[1];
    const float* nxyz = (const float*)d_in[2];
    const float* w00 = (const float*)d_in[5];
    const float* g00 = (const float*)d_in[6];
    const float* b00 = (const float*)d_in[7];
    const float* w01 = (const float*)d_in[8];
    const float* g01 = (const float*)d_in[9];
    const float* b01 = (const float*)d_in[10];
    const float* w10 = (const float*)d_in[11];
    const float* g10 = (const float*)d_in[12];
    const float* b10 = (const float*)d_in[13];
    const float* w11 = (const float*)d_in[14];
    const float* g11 = (const float*)d_in[15];
    const float* b11 = (const float*)d_in[16];

    float* outBase = (float*)d_out;
    int featOff = out_size - MTOT * 256;
    if (featOff > 0) {
        copy_kernel<<<(featOff + 255) / 256, 256>>>(nxyz, outBase, featOff);
    }
    float* outF = outBase + (featOff > 0 ? featOff : 0);

    cudaFuncSetAttribute(gemm1_tc<16>,
                         cudaFuncAttributeMaxDynamicSharedMemorySize, SMEM1B);
    cudaFuncSetAttribute(gemm1_tc<32>,
                         cudaFuncAttributeMaxDynamicSharedMemorySize, SMEM1B);
    cudaFuncSetAttribute(gemm2_tc,
                         cudaFuncAttributeMaxDynamicSharedMemorySize, SMEM2B);

    float* X0p;
    float* X1p;
    int* idxp;
    cudaGetSymbolAddress((void**)&X0p, g_X0);
    cudaGetSymbolAddress((void**)&X1p, g_X1);
    cudaGetSymbolAddress((void**)&idxp, g_idx);

    const float r2_0 = (float)(0.2 * 0.2);
    const float r2_1 = (float)(0.4 * 0.4);

    // ---------------- scale 0 (NS=16) ----------------
    {
        const int R = MTOT * 16;  // 131072
        ballquery_kernel<16><<<MTOT * 32 / 256, 256>>>(xyz, nxyz, r2_0, idxp);
        zero_stats_kernel<<<1, 128>>>();
        gemm1_tc<16><<<R / 128, 256, SMEM1B>>>(xyz, feat, nxyz, idxp, w00, X0p);
        finalize_kernel<<<1, 128>>>(g00, b00, 1.0f / (float)R);
        zero_stats_kernel<<<1, 128>>>();
        gemm2_tc<<<R / 128, 256, SMEM2B>>>(X0p, w01, X1p);
        finalize_kernel<<<1, 128>>>(g01, b01, 1.0f / (float)R);
        maxpool_kernel<16><<<MTOT * 128 / 256, 256>>>(X1p, outF, 0);
    }

    // ---------------- scale 1 (NS=32) ----------------
    {
        const int R = MTOT * 32;  // 262144
        ballquery_kernel<32><<<MTOT * 32 / 256, 256>>>(xyz, nxyz, r2_1, idxp);
        zero_stats_kernel<<<1, 128>>>();
        gemm1_tc<32><<<R / 128, 256, SMEM1B>>>(xyz, feat, nxyz, idxp, w10, X0p);
        finalize_kernel<<<1, 128>>>(g10, b10, 1.0f / (float)R);
        zero_stats_kernel<<<1, 128>>>();
        gemm2_tc<<<R / 128, 256, SMEM2B>>>(X0p, w11, X1p);
        finalize_kernel<<<1, 128>>>(g11, b11, 1.0f / (float)R);
        maxpool_kernel<32><<<MTOT * 128 / 256, 256>>>(X1p, outF, 128);
    }
}